// round 1
// baseline (speedup 1.0000x reference)
#include <cuda_runtime.h>
#include <cuda_bf16.h>

#define DIMC 1024
#define NH   16
#define HD   64
#define BB   2
#define TT   2048
#define MROWS (BB*TT)   // 4096

// Scratch (allocation-free rule: __device__ globals)
__device__ float g_Q[MROWS*DIMC];
__device__ float g_K[MROWS*DIMC];
__device__ float g_V[MROWS*DIMC];
__device__ float g_Ctx[MROWS*DIMC];

// ---------------------------------------------------------------------------
// SGEMM: C[M,N] = A[M,K] @ W[K,N] + bias[N]
// BM=64, BN=64, BK=16, 256 threads, 4x4 micro-tile per thread.
// All dims are multiples of the tiles (M=4096, N=K=1024) -> no bounds checks.
// ---------------------------------------------------------------------------
__global__ void sgemm_bias_kernel(const float* __restrict__ A,
                                  const float* __restrict__ W,
                                  const float* __restrict__ bias,
                                  float* __restrict__ C,
                                  int M, int N, int K)
{
    const int BM = 64, BN = 64, BK = 16;
    __shared__ float As[BM][BK + 1];   // +1 pad: ty-indexed reads conflict-free
    __shared__ float Bs[BK][BN];       // float4 reads along tx: conflict-free

    const int tid = threadIdx.x;
    const int tx  = tid & 15;
    const int ty  = tid >> 4;
    const int row0 = blockIdx.y * BM;
    const int col0 = blockIdx.x * BN;

    float acc[4][4] = {};

    for (int k0 = 0; k0 < K; k0 += BK) {
        // Load A tile: 64x16 = 1024 elems / 256 thr = 4 each
        #pragma unroll
        for (int t = 0; t < 4; t++) {
            int i = tid + t * 256;
            int r = i >> 4, c = i & 15;
            As[r][c] = A[(size_t)(row0 + r) * K + k0 + c];
        }
        // Load W tile: 16x64 = 1024 elems
        #pragma unroll
        for (int t = 0; t < 4; t++) {
            int i = tid + t * 256;
            int r = i >> 6, c = i & 63;
            Bs[r][c] = W[(size_t)(k0 + r) * N + col0 + c];
        }
        __syncthreads();

        #pragma unroll
        for (int kk = 0; kk < BK; kk++) {
            float a[4];
            #pragma unroll
            for (int i = 0; i < 4; i++) a[i] = As[ty * 4 + i][kk];
            float4 b4 = *reinterpret_cast<const float4*>(&Bs[kk][tx * 4]);
            float b[4] = {b4.x, b4.y, b4.z, b4.w};
            #pragma unroll
            for (int i = 0; i < 4; i++)
                #pragma unroll
                for (int j = 0; j < 4; j++)
                    acc[i][j] += a[i] * b[j];
        }
        __syncthreads();
    }

    #pragma unroll
    for (int i = 0; i < 4; i++) {
        int r = row0 + ty * 4 + i;
        #pragma unroll
        for (int j = 0; j < 4; j++) {
            int c = col0 + tx * 4 + j;
            C[(size_t)r * N + c] = acc[i][j] + bias[c];
        }
    }
}

// ---------------------------------------------------------------------------
// Flash attention (causal), fp32, online softmax.
// Grid: (T/64 q-blocks, B*H). Block: 256 threads (16x16), 4x4 micro-tiles.
// smem (dynamic): Qs[64][68], Ks_t[64(d)][68(k)], Vs[64][68], Ps[64][68]
// ---------------------------------------------------------------------------
#define ALD 68
#define ATTN_SMEM (4 * 64 * ALD * (int)sizeof(float))

__global__ void flash_attn_kernel(const float* __restrict__ Q,
                                  const float* __restrict__ K,
                                  const float* __restrict__ V,
                                  float* __restrict__ O)
{
    extern __shared__ float sm[];
    float* Qs = sm;               // [q][d]
    float* Ks = Qs + 64 * ALD;    // transposed: [d][k]
    float* Vs = Ks + 64 * ALD;    // [k][d]
    float* Ps = Vs + 64 * ALD;    // [q][k]

    const int tid = threadIdx.x;
    const int tx  = tid & 15;
    const int ty  = tid >> 4;
    const int qb  = blockIdx.x;           // 0..31
    const int bh  = blockIdx.y;           // 0..31
    const int b   = bh >> 4;
    const int h   = bh & 15;
    const int q0  = qb * 64;
    const float scale = 0.125f;           // 1/sqrt(64)

    const size_t base = (size_t)b * TT * DIMC + (size_t)h * HD;

    // Load Q tile (64x64), coalesced along d
    #pragma unroll
    for (int t = 0; t < 16; t++) {
        int i = tid + t * 256;
        int r = i >> 6, d = i & 63;
        Qs[r * ALD + d] = Q[base + (size_t)(q0 + r) * DIMC + d];
    }

    float m[4], l[4], o[4][4];
    #pragma unroll
    for (int i = 0; i < 4; i++) {
        m[i] = -1e30f; l[i] = 0.f;
        #pragma unroll
        for (int j = 0; j < 4; j++) o[i][j] = 0.f;
    }

    for (int jb = 0; jb <= qb; jb++) {
        const int k0 = jb * 64;
        __syncthreads();  // protects Qs (first iter) and Ks/Vs/Ps reuse

        // Load K (transposed in smem) + V
        #pragma unroll
        for (int t = 0; t < 16; t++) {
            int i = tid + t * 256;
            int r = i >> 6, d = i & 63;
            Ks[d * ALD + r] = K[base + (size_t)(k0 + r) * DIMC + d];
            Vs[r * ALD + d] = V[base + (size_t)(k0 + r) * DIMC + d];
        }
        __syncthreads();

        // S = Q @ K^T  (4x4 per thread)
        float s[4][4] = {};
        #pragma unroll 8
        for (int d = 0; d < 64; d++) {
            float a[4];
            #pragma unroll
            for (int i = 0; i < 4; i++) a[i] = Qs[(ty * 4 + i) * ALD + d];
            float4 k4 = *reinterpret_cast<const float4*>(&Ks[d * ALD + tx * 4]);
            float kk[4] = {k4.x, k4.y, k4.z, k4.w};
            #pragma unroll
            for (int i = 0; i < 4; i++)
                #pragma unroll
                for (int j = 0; j < 4; j++)
                    s[i][j] += a[i] * kk[j];
        }

        // scale + causal mask (only the diagonal block needs masking)
        const bool diag = (jb == qb);
        #pragma unroll
        for (int i = 0; i < 4; i++) {
            int qi = ty * 4 + i;
            #pragma unroll
            for (int j = 0; j < 4; j++) {
                int kj = tx * 4 + j;
                float v = s[i][j] * scale;
                if (diag && kj > qi) v = -1e30f;
                s[i][j] = v;
            }
        }

        // Online softmax; row stats shared by the 16 lanes of each row group
        #pragma unroll
        for (int i = 0; i < 4; i++) {
            float mx = fmaxf(fmaxf(s[i][0], s[i][1]), fmaxf(s[i][2], s[i][3]));
            #pragma unroll
            for (int off = 8; off >= 1; off >>= 1)
                mx = fmaxf(mx, __shfl_xor_sync(0xffffffffu, mx, off));
            float mnew = fmaxf(m[i], mx);
            float corr = __expf(m[i] - mnew);
            float rs = 0.f;
            #pragma unroll
            for (int j = 0; j < 4; j++) {
                float p = __expf(s[i][j] - mnew);
                s[i][j] = p;
                rs += p;
            }
            #pragma unroll
            for (int off = 8; off >= 1; off >>= 1)
                rs += __shfl_xor_sync(0xffffffffu, rs, off);
            l[i] = l[i] * corr + rs;
            m[i] = mnew;
            #pragma unroll
            for (int j = 0; j < 4; j++) o[i][j] *= corr;
        }

        // Stage P to smem for the second GEMM
        #pragma unroll
        for (int i = 0; i < 4; i++) {
            float4 p4 = make_float4(s[i][0], s[i][1], s[i][2], s[i][3]);
            *reinterpret_cast<float4*>(&Ps[(ty * 4 + i) * ALD + tx * 4]) = p4;
        }
        __syncthreads();

        // O += P @ V
        #pragma unroll 8
        for (int kj = 0; kj < 64; kj++) {
            float p[4];
            #pragma unroll
            for (int i = 0; i < 4; i++) p[i] = Ps[(ty * 4 + i) * ALD + kj];
            float4 v4 = *reinterpret_cast<const float4*>(&Vs[kj * ALD + tx * 4]);
            float vv[4] = {v4.x, v4.y, v4.z, v4.w};
            #pragma unroll
            for (int i = 0; i < 4; i++)
                #pragma unroll
                for (int j = 0; j < 4; j++)
                    o[i][j] += p[i] * vv[j];
        }
    }

    // Normalize + write ctx in [B,T,H*D] layout (fuses the head transpose)
    #pragma unroll
    for (int i = 0; i < 4; i++) {
        float inv = 1.f / l[i];
        size_t row = base + (size_t)(q0 + ty * 4 + i) * DIMC + tx * 4;
        #pragma unroll
        for (int j = 0; j < 4; j++)
            O[row + j] = o[i][j] * inv;
    }
}

// ---------------------------------------------------------------------------
extern "C" void kernel_launch(void* const* d_in, const int* in_sizes, int n_in,
                              void* d_out, int out_size)
{
    (void)in_sizes; (void)n_in; (void)out_size;
    const float* x  = (const float*)d_in[0];
    const float* Wq = (const float*)d_in[1];
    const float* bq = (const float*)d_in[2];
    const float* Wk = (const float*)d_in[3];
    const float* bk = (const float*)d_in[4];
    const float* Wv = (const float*)d_in[5];
    const float* bv = (const float*)d_in[6];
    const float* Wo = (const float*)d_in[7];
    const float* bo = (const float*)d_in[8];
    float* out = (float*)d_out;

    float *Qp, *Kp, *Vp, *Cp;
    cudaGetSymbolAddress((void**)&Qp, g_Q);
    cudaGetSymbolAddress((void**)&Kp, g_K);
    cudaGetSymbolAddress((void**)&Vp, g_V);
    cudaGetSymbolAddress((void**)&Cp, g_Ctx);

    cudaFuncSetAttribute(flash_attn_kernel,
                         cudaFuncAttributeMaxDynamicSharedMemorySize, ATTN_SMEM);

    dim3 gblk(256);
    dim3 ggrid(DIMC / 64, MROWS / 64);   // (16, 64)

    sgemm_bias_kernel<<<ggrid, gblk>>>(x,  Wq, bq, Qp, MROWS, DIMC, DIMC);
    sgemm_bias_kernel<<<ggrid, gblk>>>(x,  Wk, bk, Kp, MROWS, DIMC, DIMC);
    sgemm_bias_kernel<<<ggrid, gblk>>>(x,  Wv, bv, Vp, MROWS, DIMC, DIMC);

    dim3 agrid(TT / 64, BB * NH);        // (32, 32)
    flash_attn_kernel<<<agrid, gblk, ATTN_SMEM>>>(Qp, Kp, Vp, Cp);

    sgemm_bias_kernel<<<ggrid, gblk>>>(Cp, Wo, bo, out, MROWS, DIMC, DIMC);
}

// round 2
// speedup vs baseline: 1.9427x; 1.9427x over previous
#include <cuda_runtime.h>
#include <cstdint>

#define DIMC 1024
#define NH   16
#define HD   64
#define BB   2
#define TT   2048
#define MROWS (BB*TT)   // 4096

// Scratch (allocation-free rule: __device__ globals)
__device__ float g_Q[MROWS*DIMC];
__device__ float g_K[MROWS*DIMC];
__device__ float g_V[MROWS*DIMC];
__device__ float g_Ctx[MROWS*DIMC];
__device__ float g_Xc[MROWS*DIMC];      // tf32-rounded x
__device__ float g_Wc[4*DIMC*DIMC];     // tf32-rounded Wq,Wk,Wv,Wo

__device__ __forceinline__ unsigned f2tf32(float f) {
    unsigned r;
    asm("cvt.rna.tf32.f32 %0, %1;" : "=r"(r) : "f"(f));
    return r;
}

// ---------------------------------------------------------------------------
// Pre-pass: round x and the 4 weight matrices to tf32 (rna) once.
// ---------------------------------------------------------------------------
__global__ void cvt_all_kernel(const float* __restrict__ x,
                               const float* __restrict__ wq,
                               const float* __restrict__ wk,
                               const float* __restrict__ wv,
                               const float* __restrict__ wo,
                               float* __restrict__ xc,
                               float* __restrict__ wc)
{
    const int NX = MROWS*DIMC;          // 4M
    const int NW = DIMC*DIMC;           // 1M
    int i = blockIdx.x*blockDim.x + threadIdx.x;
    if (i < NX) {
        xc[i] = __uint_as_float(f2tf32(x[i]));
    } else {
        int j = i - NX;                 // 0 .. 4M-1
        int w = j >> 20;                // which weight
        int o = j & (NW - 1);
        const float* src = (w == 0) ? wq : (w == 1) ? wk : (w == 2) ? wv : wo;
        wc[j] = __uint_as_float(f2tf32(src[o]));
    }
}

// ---------------------------------------------------------------------------
// TF32 tensor-core GEMM: C[M,N] = A[M,K] @ W[K,N] + bias
// BM=128, BN=128, BK=32, 256 threads (8 warps, 4x2), warp tile 32x64,
// mma.sync.m16n8k8.tf32, cp.async double-buffered smem.
// As: [m][k] pad to 36 (conflict-free frag LDS + STS.128 via cp.async)
// Bs: [k][n] with XOR swizzle col ^ ((k&3)<<3) (conflict-free both ways)
// ---------------------------------------------------------------------------
#define BM 128
#define BN 128
#define BKT 32
#define AS_STRIDE 36
#define A_STAGE (BM*AS_STRIDE)            // 4608 floats
#define B_STAGE (BKT*BN)                  // 4096 floats
#define STAGE_FLOATS (A_STAGE + B_STAGE)  // 8704
#define GEMM_SMEM (2*STAGE_FLOATS*(int)sizeof(float))  // 69632 B

__global__ void __launch_bounds__(256, 2)
gemm_tf32_bias(const float* __restrict__ A, const float* __restrict__ W,
               const float* __restrict__ bias, float* __restrict__ C,
               int M, int N, int K)
{
    extern __shared__ float sm[];
    const int tid  = threadIdx.x;
    const int lane = tid & 31;
    const int warp = tid >> 5;
    const int wm   = warp >> 1;           // 0..3
    const int wn   = warp & 1;            // 0..1
    const int row0 = blockIdx.y * BM;
    const int col0 = blockIdx.x * BN;

    float acc[2][8][4];
    #pragma unroll
    for (int i = 0; i < 2; i++)
        #pragma unroll
        for (int j = 0; j < 8; j++)
            #pragma unroll
            for (int q = 0; q < 4; q++) acc[i][j][q] = 0.f;

    const int NT = K / BKT;               // 32

    // async-load one k-tile into stage s
    auto load_tile = [&](int kt, int s) {
        float* As = sm + s*STAGE_FLOATS;
        float* Bs = As + A_STAGE;
        #pragma unroll
        for (int i = 0; i < 4; i++) {
            int idx = tid + i*256;
            int r = idx >> 3, c4 = idx & 7;       // A tile: 128 rows x 8 float4
            const float* src = A + (size_t)(row0 + r)*K + kt*BKT + c4*4;
            unsigned dst = (unsigned)__cvta_generic_to_shared(&As[r*AS_STRIDE + c4*4]);
            asm volatile("cp.async.cg.shared.global [%0], [%1], 16;" :: "r"(dst), "l"(src));
        }
        #pragma unroll
        for (int i = 0; i < 4; i++) {
            int idx = tid + i*256;
            int r = idx >> 5, c4 = idx & 31;      // W tile: 32 rows x 32 float4
            int csw = (c4*4) ^ ((r & 3) << 3);
            const float* src = W + (size_t)(kt*BKT + r)*N + col0 + c4*4;
            unsigned dst = (unsigned)__cvta_generic_to_shared(&Bs[r*BN + csw]);
            asm volatile("cp.async.cg.shared.global [%0], [%1], 16;" :: "r"(dst), "l"(src));
        }
        asm volatile("cp.async.commit_group;");
    };

    load_tile(0, 0);

    for (int t = 0; t < NT; t++) {
        if (t + 1 < NT) {
            load_tile(t + 1, (t + 1) & 1);
            asm volatile("cp.async.wait_group 1;");
        } else {
            asm volatile("cp.async.wait_group 0;");
        }
        __syncthreads();

        const float* As = sm + (t & 1)*STAGE_FLOATS;
        const float* Bs = As + A_STAGE;

        #pragma unroll
        for (int kk = 0; kk < BKT; kk += 8) {
            unsigned a[2][4];
            #pragma unroll
            for (int i = 0; i < 2; i++) {
                int r = wm*32 + i*16 + (lane >> 2);
                int c = kk + (lane & 3);
                a[i][0] = __float_as_uint(As[r*AS_STRIDE + c]);
                a[i][1] = __float_as_uint(As[(r+8)*AS_STRIDE + c]);
                a[i][2] = __float_as_uint(As[r*AS_STRIDE + c + 4]);
                a[i][3] = __float_as_uint(As[(r+8)*AS_STRIDE + c + 4]);
            }
            unsigned b[8][2];
            #pragma unroll
            for (int j = 0; j < 8; j++) {
                int n  = wn*64 + j*8 + (lane >> 2);
                int r0 = kk + (lane & 3);
                int r1 = r0 + 4;
                b[j][0] = __float_as_uint(Bs[r0*BN + (n ^ ((r0 & 3) << 3))]);
                b[j][1] = __float_as_uint(Bs[r1*BN + (n ^ ((r1 & 3) << 3))]);
            }
            #pragma unroll
            for (int i = 0; i < 2; i++)
                #pragma unroll
                for (int j = 0; j < 8; j++)
                    asm volatile(
                        "mma.sync.aligned.m16n8k8.row.col.f32.tf32.tf32.f32 "
                        "{%0,%1,%2,%3}, {%4,%5,%6,%7}, {%8,%9}, {%0,%1,%2,%3};"
                        : "+f"(acc[i][j][0]), "+f"(acc[i][j][1]),
                          "+f"(acc[i][j][2]), "+f"(acc[i][j][3])
                        : "r"(a[i][0]), "r"(a[i][1]), "r"(a[i][2]), "r"(a[i][3]),
                          "r"(b[j][0]), "r"(b[j][1]));
        }
        __syncthreads();
    }

    // epilogue
    #pragma unroll
    for (int i = 0; i < 2; i++) {
        int r = row0 + wm*32 + i*16 + (lane >> 2);
        #pragma unroll
        for (int j = 0; j < 8; j++) {
            int c = col0 + wn*64 + j*8 + (lane & 3)*2;
            float b0 = bias[c], b1 = bias[c+1];
            C[(size_t)r*N + c]       = acc[i][j][0] + b0;
            C[(size_t)r*N + c + 1]   = acc[i][j][1] + b1;
            C[(size_t)(r+8)*N + c]   = acc[i][j][2] + b0;
            C[(size_t)(r+8)*N + c+1] = acc[i][j][3] + b1;
        }
    }
}

// ---------------------------------------------------------------------------
// Flash attention (causal), fp32, online softmax. (unchanged from R1 except
// epilogue rounds ctx to tf32 — it feeds the tf32 output GEMM)
// ---------------------------------------------------------------------------
#define ALD 68
#define ATTN_SMEM (4 * 64 * ALD * (int)sizeof(float))

__global__ void flash_attn_kernel(const float* __restrict__ Q,
                                  const float* __restrict__ K,
                                  const float* __restrict__ V,
                                  float* __restrict__ O)
{
    extern __shared__ float smf[];
    float* Qs = smf;              // [q][d]
    float* Ks = Qs + 64 * ALD;    // transposed: [d][k]
    float* Vs = Ks + 64 * ALD;    // [k][d]
    float* Ps = Vs + 64 * ALD;    // [q][k]

    const int tid = threadIdx.x;
    const int tx  = tid & 15;
    const int ty  = tid >> 4;
    const int qb  = blockIdx.x;
    const int bh  = blockIdx.y;
    const int b   = bh >> 4;
    const int h   = bh & 15;
    const int q0  = qb * 64;
    const float scale = 0.125f;

    const size_t base = (size_t)b * TT * DIMC + (size_t)h * HD;

    #pragma unroll
    for (int t = 0; t < 16; t++) {
        int i = tid + t * 256;
        int r = i >> 6, d = i & 63;
        Qs[r * ALD + d] = Q[base + (size_t)(q0 + r) * DIMC + d];
    }

    float m[4], l[4], o[4][4];
    #pragma unroll
    for (int i = 0; i < 4; i++) {
        m[i] = -1e30f; l[i] = 0.f;
        #pragma unroll
        for (int j = 0; j < 4; j++) o[i][j] = 0.f;
    }

    for (int jb = 0; jb <= qb; jb++) {
        const int k0 = jb * 64;
        __syncthreads();

        #pragma unroll
        for (int t = 0; t < 16; t++) {
            int i = tid + t * 256;
            int r = i >> 6, d = i & 63;
            Ks[d * ALD + r] = K[base + (size_t)(k0 + r) * DIMC + d];
            Vs[r * ALD + d] = V[base + (size_t)(k0 + r) * DIMC + d];
        }
        __syncthreads();

        float s[4][4] = {};
        #pragma unroll 8
        for (int d = 0; d < 64; d++) {
            float a[4];
            #pragma unroll
            for (int i = 0; i < 4; i++) a[i] = Qs[(ty * 4 + i) * ALD + d];
            float4 k4 = *reinterpret_cast<const float4*>(&Ks[d * ALD + tx * 4]);
            float kk[4] = {k4.x, k4.y, k4.z, k4.w};
            #pragma unroll
            for (int i = 0; i < 4; i++)
                #pragma unroll
                for (int j = 0; j < 4; j++)
                    s[i][j] += a[i] * kk[j];
        }

        const bool diag = (jb == qb);
        #pragma unroll
        for (int i = 0; i < 4; i++) {
            int qi = ty * 4 + i;
            #pragma unroll
            for (int j = 0; j < 4; j++) {
                int kj = tx * 4 + j;
                float v = s[i][j] * scale;
                if (diag && kj > qi) v = -1e30f;
                s[i][j] = v;
            }
        }

        #pragma unroll
        for (int i = 0; i < 4; i++) {
            float mx = fmaxf(fmaxf(s[i][0], s[i][1]), fmaxf(s[i][2], s[i][3]));
            #pragma unroll
            for (int off = 8; off >= 1; off >>= 1)
                mx = fmaxf(mx, __shfl_xor_sync(0xffffffffu, mx, off));
            float mnew = fmaxf(m[i], mx);
            float corr = __expf(m[i] - mnew);
            float rs = 0.f;
            #pragma unroll
            for (int j = 0; j < 4; j++) {
                float p = __expf(s[i][j] - mnew);
                s[i][j] = p;
                rs += p;
            }
            #pragma unroll
            for (int off = 8; off >= 1; off >>= 1)
                rs += __shfl_xor_sync(0xffffffffu, rs, off);
            l[i] = l[i] * corr + rs;
            m[i] = mnew;
            #pragma unroll
            for (int j = 0; j < 4; j++) o[i][j] *= corr;
        }

        #pragma unroll
        for (int i = 0; i < 4; i++) {
            float4 p4 = make_float4(s[i][0], s[i][1], s[i][2], s[i][3]);
            *reinterpret_cast<float4*>(&Ps[(ty * 4 + i) * ALD + tx * 4]) = p4;
        }
        __syncthreads();

        #pragma unroll 8
        for (int kj = 0; kj < 64; kj++) {
            float p[4];
            #pragma unroll
            for (int i = 0; i < 4; i++) p[i] = Ps[(ty * 4 + i) * ALD + kj];
            float4 v4 = *reinterpret_cast<const float4*>(&Vs[kj * ALD + tx * 4]);
            float vv[4] = {v4.x, v4.y, v4.z, v4.w};
            #pragma unroll
            for (int i = 0; i < 4; i++)
                #pragma unroll
                for (int j = 0; j < 4; j++)
                    o[i][j] += p[i] * vv[j];
        }
    }

    // Normalize + write ctx (tf32-rounded; feeds tf32 GEMM) in [B,T,H*D]
    #pragma unroll
    for (int i = 0; i < 4; i++) {
        float inv = 1.f / l[i];
        size_t row = base + (size_t)(q0 + ty * 4 + i) * DIMC + tx * 4;
        #pragma unroll
        for (int j = 0; j < 4; j++)
            O[row + j] = __uint_as_float(f2tf32(o[i][j] * inv));
    }
}

// ---------------------------------------------------------------------------
extern "C" void kernel_launch(void* const* d_in, const int* in_sizes, int n_in,
                              void* d_out, int out_size)
{
    (void)in_sizes; (void)n_in; (void)out_size;
    const float* x  = (const float*)d_in[0];
    const float* Wq = (const float*)d_in[1];
    const float* bq = (const float*)d_in[2];
    const float* Wk = (const float*)d_in[3];
    const float* bk = (const float*)d_in[4];
    const float* Wv = (const float*)d_in[5];
    const float* bv = (const float*)d_in[6];
    const float* Wo = (const float*)d_in[7];
    const float* bo = (const float*)d_in[8];
    float* out = (float*)d_out;

    float *Qp, *Kp, *Vp, *Cp, *Xc, *Wc;
    cudaGetSymbolAddress((void**)&Qp, g_Q);
    cudaGetSymbolAddress((void**)&Kp, g_K);
    cudaGetSymbolAddress((void**)&Vp, g_V);
    cudaGetSymbolAddress((void**)&Cp, g_Ctx);
    cudaGetSymbolAddress((void**)&Xc, g_Xc);
    cudaGetSymbolAddress((void**)&Wc, g_Wc);

    cudaFuncSetAttribute(gemm_tf32_bias,
                         cudaFuncAttributeMaxDynamicSharedMemorySize, GEMM_SMEM);
    cudaFuncSetAttribute(flash_attn_kernel,
                         cudaFuncAttributeMaxDynamicSharedMemorySize, ATTN_SMEM);

    // pre-round x + weights to tf32
    const int NTOT = MROWS*DIMC + 4*DIMC*DIMC;   // 8M
    cvt_all_kernel<<<NTOT/256, 256>>>(x, Wq, Wk, Wv, Wo, Xc, Wc);

    dim3 gblk(256);
    dim3 ggrid(DIMC / BN, MROWS / BM);   // (8, 32)
    const int NW = DIMC*DIMC;

    gemm_tf32_bias<<<ggrid, gblk, GEMM_SMEM>>>(Xc, Wc + 0*NW, bq, Qp, MROWS, DIMC, DIMC);
    gemm_tf32_bias<<<ggrid, gblk, GEMM_SMEM>>>(Xc, Wc + 1*NW, bk, Kp, MROWS, DIMC, DIMC);
    gemm_tf32_bias<<<ggrid, gblk, GEMM_SMEM>>>(Xc, Wc + 2*NW, bv, Vp, MROWS, DIMC, DIMC);

    dim3 agrid(TT / 64, BB * NH);        // (32, 32)
    flash_attn_kernel<<<agrid, gblk, ATTN_SMEM>>>(Qp, Kp, Vp, Cp);

    gemm_tf32_bias<<<ggrid, gblk, GEMM_SMEM>>>(Cp, Wc + 3*NW, bo, out, MROWS, DIMC, DIMC);
}

// round 3
// speedup vs baseline: 3.7747x; 1.9431x over previous
#include <cuda_runtime.h>
#include <cstdint>

#define DIMC 1024
#define NH   16
#define HD   64
#define BB   2
#define TT   2048
#define MROWS (BB*TT)   // 4096

// Scratch (allocation-free rule: __device__ globals)
__device__ float g_QKV[3*MROWS*DIMC];
__device__ float g_Ctx[MROWS*DIMC];
__device__ float g_Xc[MROWS*DIMC];      // tf32-rounded x
__device__ float g_Wc[4*DIMC*DIMC];     // tf32-rounded Wq,Wk,Wv,Wo

__device__ __forceinline__ unsigned f2tf32(float f) {
    unsigned r;
    asm("cvt.rna.tf32.f32 %0, %1;" : "=r"(r) : "f"(f));
    return r;
}
__device__ __forceinline__ float fexp2(float x) {
    float y;
    asm("ex2.approx.f32 %0, %1;" : "=f"(y) : "f"(x));
    return y;
}

// ---------------------------------------------------------------------------
// Pre-pass: round x and the 4 weight matrices to tf32 (rna) once.
// ---------------------------------------------------------------------------
__global__ void cvt_all_kernel(const float* __restrict__ x,
                               const float* __restrict__ wq,
                               const float* __restrict__ wk,
                               const float* __restrict__ wv,
                               const float* __restrict__ wo,
                               float* __restrict__ xc,
                               float* __restrict__ wc)
{
    const int NX = MROWS*DIMC;          // 4M
    const int NW = DIMC*DIMC;           // 1M
    int i = blockIdx.x*blockDim.x + threadIdx.x;
    if (i < NX) {
        xc[i] = __uint_as_float(f2tf32(x[i]));
    } else {
        int j = i - NX;
        int w = j >> 20;
        int o = j & (NW - 1);
        const float* src = (w == 0) ? wq : (w == 1) ? wk : (w == 2) ? wv : wo;
        wc[j] = __uint_as_float(f2tf32(src[o]));
    }
}

// ---------------------------------------------------------------------------
// TF32 tensor-core GEMM: C[M,N] = A @ W[z] + bias[z]; grid.z selects weight.
// BM=128, BN=128, BK=32, 256 threads (8 warps, 4x2), warp tile 32x64.
// ---------------------------------------------------------------------------
#define BM 128
#define BN 128
#define BKT 32
#define AS_STRIDE 36
#define A_STAGE (BM*AS_STRIDE)
#define B_STAGE (BKT*BN)
#define STAGE_FLOATS (A_STAGE + B_STAGE)
#define GEMM_SMEM (2*STAGE_FLOATS*(int)sizeof(float))

__global__ void __launch_bounds__(256, 2)
gemm_tf32_bias(const float* __restrict__ A, const float* __restrict__ Wall,
               const float* __restrict__ b0p, const float* __restrict__ b1p,
               const float* __restrict__ b2p, float* __restrict__ Cbase,
               int M, int N, int K, int round_out)
{
    extern __shared__ float sm[];
    const int z = blockIdx.z;
    const float* W    = Wall + (size_t)z*N*K;
    const float* bias = (z == 0) ? b0p : (z == 1) ? b1p : b2p;
    float* C          = Cbase + (size_t)z*M*N;

    const int tid  = threadIdx.x;
    const int lane = tid & 31;
    const int warp = tid >> 5;
    const int wm   = warp >> 1;
    const int wn   = warp & 1;
    const int row0 = blockIdx.y * BM;
    const int col0 = blockIdx.x * BN;

    float acc[2][8][4];
    #pragma unroll
    for (int i = 0; i < 2; i++)
        #pragma unroll
        for (int j = 0; j < 8; j++)
            #pragma unroll
            for (int q = 0; q < 4; q++) acc[i][j][q] = 0.f;

    const int NT = K / BKT;

    auto load_tile = [&](int kt, int s) {
        float* As = sm + s*STAGE_FLOATS;
        float* Bs = As + A_STAGE;
        #pragma unroll
        for (int i = 0; i < 4; i++) {
            int idx = tid + i*256;
            int r = idx >> 3, c4 = idx & 7;
            const float* src = A + (size_t)(row0 + r)*K + kt*BKT + c4*4;
            unsigned dst = (unsigned)__cvta_generic_to_shared(&As[r*AS_STRIDE + c4*4]);
            asm volatile("cp.async.cg.shared.global [%0], [%1], 16;" :: "r"(dst), "l"(src));
        }
        #pragma unroll
        for (int i = 0; i < 4; i++) {
            int idx = tid + i*256;
            int r = idx >> 5, c4 = idx & 31;
            int csw = (c4*4) ^ ((r & 3) << 3);
            const float* src = W + (size_t)(kt*BKT + r)*N + col0 + c4*4;
            unsigned dst = (unsigned)__cvta_generic_to_shared(&Bs[r*BN + csw]);
            asm volatile("cp.async.cg.shared.global [%0], [%1], 16;" :: "r"(dst), "l"(src));
        }
        asm volatile("cp.async.commit_group;");
    };

    load_tile(0, 0);

    for (int t = 0; t < NT; t++) {
        if (t + 1 < NT) {
            load_tile(t + 1, (t + 1) & 1);
            asm volatile("cp.async.wait_group 1;");
        } else {
            asm volatile("cp.async.wait_group 0;");
        }
        __syncthreads();

        const float* As = sm + (t & 1)*STAGE_FLOATS;
        const float* Bs = As + A_STAGE;

        #pragma unroll
        for (int kk = 0; kk < BKT; kk += 8) {
            unsigned a[2][4];
            #pragma unroll
            for (int i = 0; i < 2; i++) {
                int r = wm*32 + i*16 + (lane >> 2);
                int c = kk + (lane & 3);
                a[i][0] = __float_as_uint(As[r*AS_STRIDE + c]);
                a[i][1] = __float_as_uint(As[(r+8)*AS_STRIDE + c]);
                a[i][2] = __float_as_uint(As[r*AS_STRIDE + c + 4]);
                a[i][3] = __float_as_uint(As[(r+8)*AS_STRIDE + c + 4]);
            }
            unsigned b[8][2];
            #pragma unroll
            for (int j = 0; j < 8; j++) {
                int n  = wn*64 + j*8 + (lane >> 2);
                int r0 = kk + (lane & 3);
                int r1 = r0 + 4;
                b[j][0] = __float_as_uint(Bs[r0*BN + (n ^ ((r0 & 3) << 3))]);
                b[j][1] = __float_as_uint(Bs[r1*BN + (n ^ ((r1 & 3) << 3))]);
            }
            #pragma unroll
            for (int i = 0; i < 2; i++)
                #pragma unroll
                for (int j = 0; j < 8; j++)
                    asm volatile(
                        "mma.sync.aligned.m16n8k8.row.col.f32.tf32.tf32.f32 "
                        "{%0,%1,%2,%3}, {%4,%5,%6,%7}, {%8,%9}, {%0,%1,%2,%3};"
                        : "+f"(acc[i][j][0]), "+f"(acc[i][j][1]),
                          "+f"(acc[i][j][2]), "+f"(acc[i][j][3])
                        : "r"(a[i][0]), "r"(a[i][1]), "r"(a[i][2]), "r"(a[i][3]),
                          "r"(b[j][0]), "r"(b[j][1]));
        }
        __syncthreads();
    }

    #pragma unroll
    for (int i = 0; i < 2; i++) {
        int r = row0 + wm*32 + i*16 + (lane >> 2);
        #pragma unroll
        for (int j = 0; j < 8; j++) {
            int c = col0 + wn*64 + j*8 + (lane & 3)*2;
            float b0 = bias[c], b1 = bias[c+1];
            float v0 = acc[i][j][0] + b0, v1 = acc[i][j][1] + b1;
            float v2 = acc[i][j][2] + b0, v3 = acc[i][j][3] + b1;
            if (round_out) {
                v0 = __uint_as_float(f2tf32(v0));
                v1 = __uint_as_float(f2tf32(v1));
                v2 = __uint_as_float(f2tf32(v2));
                v3 = __uint_as_float(f2tf32(v3));
            }
            C[(size_t)r*N + c]       = v0;
            C[(size_t)r*N + c + 1]   = v1;
            C[(size_t)(r+8)*N + c]   = v2;
            C[(size_t)(r+8)*N + c+1] = v3;
        }
    }
}

// ---------------------------------------------------------------------------
// Tensor-core flash attention (causal), tf32 MMA + online softmax.
// CTA: 256 threads (8 warps), 128 q-rows (16/warp), kv blocks of 64, D=64.
// smem: Qs[128][68], Ks[2][64][68], Vs[2][64][72], Ps[128][68]
// ---------------------------------------------------------------------------
#define AQ_LD 68
#define AK_LD 68
#define AV_LD 72
#define AP_LD 68
#define Q_FLOATS (128*AQ_LD)
#define K_FLOATS (64*AK_LD)
#define V_FLOATS (64*AV_LD)
#define P_FLOATS (128*AP_LD)
#define ATTN_SMEM ((Q_FLOATS + 2*K_FLOATS + 2*V_FLOATS + P_FLOATS)*(int)sizeof(float))

__global__ void __launch_bounds__(256, 1)
flash_tc_kernel(const float* __restrict__ Q, const float* __restrict__ K,
                const float* __restrict__ V, float* __restrict__ O)
{
    extern __shared__ float sm[];
    float* Qs  = sm;
    float* Ks0 = Qs  + Q_FLOATS;
    float* Vs0 = Ks0 + 2*K_FLOATS;
    float* Ps  = Vs0 + 2*V_FLOATS;

    const int tid  = threadIdx.x;
    const int lane = tid & 31;
    const int warp = tid >> 5;
    const int qb   = blockIdx.x;          // 0..15
    const int bh   = blockIdx.y;          // 0..31
    const int b    = bh >> 4;
    const int h    = bh & 15;
    const int q0   = qb * 128;
    const int qrow = warp * 16;           // warp's local q base
    const float SCL = 0.125f * 1.4426950408889634f;  // scale * log2(e)

    const size_t base = (size_t)b * TT * DIMC + (size_t)h * HD;

    // Q tile: 128 x 64 -> 2048 float4, 8 per thread (cp.async)
    #pragma unroll
    for (int i = 0; i < 8; i++) {
        int idx = tid + i*256;
        int r = idx >> 4, c4 = idx & 15;
        const float* src = Q + base + (size_t)(q0 + r)*DIMC + c4*4;
        unsigned dst = (unsigned)__cvta_generic_to_shared(&Qs[r*AQ_LD + c4*4]);
        asm volatile("cp.async.cg.shared.global [%0], [%1], 16;" :: "r"(dst), "l"(src));
    }

    auto load_kv = [&](int it, int s) {
        const int k0 = it * 64;
        float* Ks = Ks0 + s*K_FLOATS;
        float* Vs = Vs0 + s*V_FLOATS;
        #pragma unroll
        for (int i = 0; i < 4; i++) {
            int idx = tid + i*256;
            int r = idx >> 4, c4 = idx & 15;
            const float* srck = K + base + (size_t)(k0 + r)*DIMC + c4*4;
            unsigned dstk = (unsigned)__cvta_generic_to_shared(&Ks[r*AK_LD + c4*4]);
            asm volatile("cp.async.cg.shared.global [%0], [%1], 16;" :: "r"(dstk), "l"(srck));
            const float* srcv = V + base + (size_t)(k0 + r)*DIMC + c4*4;
            unsigned dstv = (unsigned)__cvta_generic_to_shared(&Vs[r*AV_LD + c4*4]);
            asm volatile("cp.async.cg.shared.global [%0], [%1], 16;" :: "r"(dstv), "l"(srcv));
        }
        asm volatile("cp.async.commit_group;");
    };

    const int niter = 2 * (qb + 1);
    load_kv(0, 0);     // same group as Q

    // Per-thread state: rows r0 = lane>>2 and r0+8 of the warp tile
    float m[2] = {-1e30f, -1e30f};
    float l[2] = {0.f, 0.f};
    float o[8][4];
    #pragma unroll
    for (int j = 0; j < 8; j++)
        #pragma unroll
        for (int q = 0; q < 4; q++) o[j][q] = 0.f;

    for (int it = 0; it < niter; it++) {
        asm volatile("cp.async.wait_group 0;");
        __syncthreads();
        if (it + 1 < niter) load_kv(it + 1, (it + 1) & 1);

        const float* Ks = Ks0 + (it & 1)*K_FLOATS;
        const float* Vs = Vs0 + (it & 1)*V_FLOATS;
        const int k0 = it * 64;

        // ---- S = Q @ K^T : 8 n-tiles (kv) x 8 k-steps (d) ----
        float s[8][4];
        #pragma unroll
        for (int j = 0; j < 8; j++)
            #pragma unroll
            for (int q = 0; q < 4; q++) s[j][q] = 0.f;

        #pragma unroll
        for (int kk = 0; kk < 8; kk++) {
            unsigned a[4];
            {
                int r = qrow + (lane >> 2);
                int c = kk*8 + (lane & 3);
                a[0] = __float_as_uint(Qs[r*AQ_LD + c]);
                a[1] = __float_as_uint(Qs[(r+8)*AQ_LD + c]);
                a[2] = __float_as_uint(Qs[r*AQ_LD + c + 4]);
                a[3] = __float_as_uint(Qs[(r+8)*AQ_LD + c + 4]);
            }
            #pragma unroll
            for (int j = 0; j < 8; j++) {
                int kv = j*8 + (lane >> 2);
                int d  = kk*8 + (lane & 3);
                unsigned b0 = __float_as_uint(Ks[kv*AK_LD + d]);
                unsigned b1 = __float_as_uint(Ks[kv*AK_LD + d + 4]);
                asm volatile(
                    "mma.sync.aligned.m16n8k8.row.col.f32.tf32.tf32.f32 "
                    "{%0,%1,%2,%3}, {%4,%5,%6,%7}, {%8,%9}, {%0,%1,%2,%3};"
                    : "+f"(s[j][0]), "+f"(s[j][1]), "+f"(s[j][2]), "+f"(s[j][3])
                    : "r"(a[0]), "r"(a[1]), "r"(a[2]), "r"(a[3]),
                      "r"(b0), "r"(b1));
            }
        }

        // ---- scale (exp2 domain) + causal mask ----
        const bool need_mask = (k0 + 63 > q0 + qrow);
        if (need_mask) {
            #pragma unroll
            for (int j = 0; j < 8; j++) {
                int kvb = k0 + j*8 + 2*(lane & 3);
                int qg0 = q0 + qrow + (lane >> 2);
                int qg1 = qg0 + 8;
                s[j][0] = (kvb     <= qg0) ? s[j][0]*SCL : -1e30f;
                s[j][1] = (kvb + 1 <= qg0) ? s[j][1]*SCL : -1e30f;
                s[j][2] = (kvb     <= qg1) ? s[j][2]*SCL : -1e30f;
                s[j][3] = (kvb + 1 <= qg1) ? s[j][3]*SCL : -1e30f;
            }
        } else {
            #pragma unroll
            for (int j = 0; j < 8; j++)
                #pragma unroll
                for (int q = 0; q < 4; q++) s[j][q] *= SCL;
        }

        // ---- online softmax (2 rows per thread) ----
        #pragma unroll
        for (int row = 0; row < 2; row++) {
            float mx = -1e30f;
            #pragma unroll
            for (int j = 0; j < 8; j++)
                mx = fmaxf(mx, fmaxf(s[j][row*2], s[j][row*2+1]));
            mx = fmaxf(mx, __shfl_xor_sync(0xffffffffu, mx, 1));
            mx = fmaxf(mx, __shfl_xor_sync(0xffffffffu, mx, 2));
            float mnew = fmaxf(m[row], mx);
            float corr = fexp2(m[row] - mnew);
            m[row] = mnew;
            float rs = 0.f;
            #pragma unroll
            for (int j = 0; j < 8; j++) {
                float p0 = fexp2(s[j][row*2]   - mnew);
                float p1 = fexp2(s[j][row*2+1] - mnew);
                s[j][row*2]   = p0;
                s[j][row*2+1] = p1;
                rs += p0 + p1;
            }
            rs += __shfl_xor_sync(0xffffffffu, rs, 1);
            rs += __shfl_xor_sync(0xffffffffu, rs, 2);
            l[row] = l[row]*corr + rs;
            #pragma unroll
            for (int j = 0; j < 8; j++) {
                o[j][row*2]   *= corr;
                o[j][row*2+1] *= corr;
            }
        }

        // ---- stage P (tf32-rounded) to smem for the PV MMA ----
        #pragma unroll
        for (int j = 0; j < 8; j++) {
            int r0 = qrow + (lane >> 2);
            int c  = j*8 + 2*(lane & 3);
            float2 p01 = make_float2(__uint_as_float(f2tf32(s[j][0])),
                                     __uint_as_float(f2tf32(s[j][1])));
            float2 p23 = make_float2(__uint_as_float(f2tf32(s[j][2])),
                                     __uint_as_float(f2tf32(s[j][3])));
            *reinterpret_cast<float2*>(&Ps[r0*AP_LD + c])     = p01;
            *reinterpret_cast<float2*>(&Ps[(r0+8)*AP_LD + c]) = p23;
        }
        __syncwarp();

        // ---- O += P @ V : 8 n-tiles (d) x 8 k-steps (kv) ----
        #pragma unroll
        for (int kk = 0; kk < 8; kk++) {
            unsigned a[4];
            {
                int r = qrow + (lane >> 2);
                int c = kk*8 + (lane & 3);
                a[0] = __float_as_uint(Ps[r*AP_LD + c]);
                a[1] = __float_as_uint(Ps[(r+8)*AP_LD + c]);
                a[2] = __float_as_uint(Ps[r*AP_LD + c + 4]);
                a[3] = __float_as_uint(Ps[(r+8)*AP_LD + c + 4]);
            }
            #pragma unroll
            for (int j = 0; j < 8; j++) {
                int kv = kk*8 + (lane & 3);
                int d  = j*8 + (lane >> 2);
                unsigned b0 = __float_as_uint(Vs[kv*AV_LD + d]);
                unsigned b1 = __float_as_uint(Vs[(kv+4)*AV_LD + d]);
                asm volatile(
                    "mma.sync.aligned.m16n8k8.row.col.f32.tf32.tf32.f32 "
                    "{%0,%1,%2,%3}, {%4,%5,%6,%7}, {%8,%9}, {%0,%1,%2,%3};"
                    : "+f"(o[j][0]), "+f"(o[j][1]), "+f"(o[j][2]), "+f"(o[j][3])
                    : "r"(a[0]), "r"(a[1]), "r"(a[2]), "r"(a[3]),
                      "r"(b0), "r"(b1));
            }
        }
        __syncthreads();
    }

    // ---- normalize + write ctx (tf32-rounded; feeds Wo GEMM) ----
    #pragma unroll
    for (int row = 0; row < 2; row++) {
        float inv = 1.f / l[row];
        int r = q0 + qrow + (lane >> 2) + row*8;
        #pragma unroll
        for (int j = 0; j < 8; j++) {
            int c = j*8 + 2*(lane & 3);
            float2 v;
            v.x = __uint_as_float(f2tf32(o[j][row*2]   * inv));
            v.y = __uint_as_float(f2tf32(o[j][row*2+1] * inv));
            *reinterpret_cast<float2*>(&O[base + (size_t)r*DIMC + c]) = v;
        }
    }
}

// ---------------------------------------------------------------------------
extern "C" void kernel_launch(void* const* d_in, const int* in_sizes, int n_in,
                              void* d_out, int out_size)
{
    (void)in_sizes; (void)n_in; (void)out_size;
    const float* x  = (const float*)d_in[0];
    const float* Wq = (const float*)d_in[1];
    const float* bq = (const float*)d_in[2];
    const float* Wk = (const float*)d_in[3];
    const float* bk = (const float*)d_in[4];
    const float* Wv = (const float*)d_in[5];
    const float* bv = (const float*)d_in[6];
    const float* Wo = (const float*)d_in[7];
    const float* bo = (const float*)d_in[8];
    float* out = (float*)d_out;

    float *QKVp, *Cp, *Xc, *Wc;
    cudaGetSymbolAddress((void**)&QKVp, g_QKV);
    cudaGetSymbolAddress((void**)&Cp,   g_Ctx);
    cudaGetSymbolAddress((void**)&Xc,   g_Xc);
    cudaGetSymbolAddress((void**)&Wc,   g_Wc);

    cudaFuncSetAttribute(gemm_tf32_bias,
                         cudaFuncAttributeMaxDynamicSharedMemorySize, GEMM_SMEM);
    cudaFuncSetAttribute(flash_tc_kernel,
                         cudaFuncAttributeMaxDynamicSharedMemorySize, ATTN_SMEM);

    const int NTOT = MROWS*DIMC + 4*DIMC*DIMC;   // 8M
    cvt_all_kernel<<<NTOT/256, 256>>>(x, Wq, Wk, Wv, Wo, Xc, Wc);

    const int NW = DIMC*DIMC;
    const int MD = MROWS*DIMC;
    dim3 gblk(256);

    // fused QKV projections (grid.z selects weight), outputs tf32-rounded
    dim3 ggrid3(DIMC / BN, MROWS / BM, 3);
    gemm_tf32_bias<<<ggrid3, gblk, GEMM_SMEM>>>(Xc, Wc, bq, bk, bv, QKVp,
                                                MROWS, DIMC, DIMC, 1);

    dim3 agrid(TT / 128, BB * NH);       // (16, 32)
    flash_tc_kernel<<<agrid, gblk, ATTN_SMEM>>>(QKVp, QKVp + MD, QKVp + 2*MD, Cp);

    dim3 ggrid1(DIMC / BN, MROWS / BM, 1);
    gemm_tf32_bias<<<ggrid1, gblk, GEMM_SMEM>>>(Cp, Wc + 3*NW, bo, bo, bo, out,
                                                MROWS, DIMC, DIMC, 0);
}

// round 4
// speedup vs baseline: 3.9771x; 1.0536x over previous
#include <cuda_runtime.h>
#include <cstdint>

#define DIMC 1024
#define NH   16
#define HD   64
#define BB   2
#define TT   2048
#define MROWS (BB*TT)   // 4096

// Scratch (allocation-free rule: __device__ globals)
__device__ float g_QKV[3*MROWS*DIMC];
__device__ float g_Ctx[MROWS*DIMC];
__device__ float g_Xc[MROWS*DIMC];      // tf32-rounded x
__device__ float g_Wc[4*DIMC*DIMC];     // tf32-rounded Wq,Wk,Wv,Wo

__device__ __forceinline__ unsigned f2tf32(float f) {
    unsigned r;
    asm("cvt.rna.tf32.f32 %0, %1;" : "=r"(r) : "f"(f));
    return r;
}
__device__ __forceinline__ float fexp2(float x) {
    float y;
    asm("ex2.approx.f32 %0, %1;" : "=f"(y) : "f"(x));
    return y;
}

// ---------------------------------------------------------------------------
// Pre-pass: round x and the 4 weight matrices to tf32 (rna) once.
// ---------------------------------------------------------------------------
__global__ void cvt_all_kernel(const float* __restrict__ x,
                               const float* __restrict__ wq,
                               const float* __restrict__ wk,
                               const float* __restrict__ wv,
                               const float* __restrict__ wo,
                               float* __restrict__ xc,
                               float* __restrict__ wc)
{
    const int NX = MROWS*DIMC;          // 4M
    const int NW = DIMC*DIMC;           // 1M
    int i = blockIdx.x*blockDim.x + threadIdx.x;
    if (i < NX) {
        xc[i] = __uint_as_float(f2tf32(x[i]));
    } else {
        int j = i - NX;
        int w = j >> 20;
        int o = j & (NW - 1);
        const float* src = (w == 0) ? wq : (w == 1) ? wk : (w == 2) ? wv : wo;
        wc[j] = __uint_as_float(f2tf32(src[o]));
    }
}

// ---------------------------------------------------------------------------
// TF32 tensor-core GEMM: C[M,N] = A @ W[z] + bias[z]; grid.z selects weight.
// BM=128, BN=128, BK=32, 256 threads (8 warps, 4x2), warp tile 32x64.
// (unchanged from R3 — proven at ~60us/GEMM)
// ---------------------------------------------------------------------------
#define BM 128
#define BN 128
#define BKT 32
#define AS_STRIDE 36
#define A_STAGE (BM*AS_STRIDE)
#define B_STAGE (BKT*BN)
#define STAGE_FLOATS (A_STAGE + B_STAGE)
#define GEMM_SMEM (2*STAGE_FLOATS*(int)sizeof(float))

__global__ void __launch_bounds__(256, 2)
gemm_tf32_bias(const float* __restrict__ A, const float* __restrict__ Wall,
               const float* __restrict__ b0p, const float* __restrict__ b1p,
               const float* __restrict__ b2p, float* __restrict__ Cbase,
               int M, int N, int K, int round_out)
{
    extern __shared__ float sm[];
    const int z = blockIdx.z;
    const float* W    = Wall + (size_t)z*N*K;
    const float* bias = (z == 0) ? b0p : (z == 1) ? b1p : b2p;
    float* C          = Cbase + (size_t)z*M*N;

    const int tid  = threadIdx.x;
    const int lane = tid & 31;
    const int warp = tid >> 5;
    const int wm   = warp >> 1;
    const int wn   = warp & 1;
    const int row0 = blockIdx.y * BM;
    const int col0 = blockIdx.x * BN;

    float acc[2][8][4];
    #pragma unroll
    for (int i = 0; i < 2; i++)
        #pragma unroll
        for (int j = 0; j < 8; j++)
            #pragma unroll
            for (int q = 0; q < 4; q++) acc[i][j][q] = 0.f;

    const int NT = K / BKT;

    auto load_tile = [&](int kt, int s) {
        float* As = sm + s*STAGE_FLOATS;
        float* Bs = As + A_STAGE;
        #pragma unroll
        for (int i = 0; i < 4; i++) {
            int idx = tid + i*256;
            int r = idx >> 3, c4 = idx & 7;
            const float* src = A + (size_t)(row0 + r)*K + kt*BKT + c4*4;
            unsigned dst = (unsigned)__cvta_generic_to_shared(&As[r*AS_STRIDE + c4*4]);
            asm volatile("cp.async.cg.shared.global [%0], [%1], 16;" :: "r"(dst), "l"(src));
        }
        #pragma unroll
        for (int i = 0; i < 4; i++) {
            int idx = tid + i*256;
            int r = idx >> 5, c4 = idx & 31;
            int csw = (c4*4) ^ ((r & 3) << 3);
            const float* src = W + (size_t)(kt*BKT + r)*N + col0 + c4*4;
            unsigned dst = (unsigned)__cvta_generic_to_shared(&Bs[r*BN + csw]);
            asm volatile("cp.async.cg.shared.global [%0], [%1], 16;" :: "r"(dst), "l"(src));
        }
        asm volatile("cp.async.commit_group;");
    };

    load_tile(0, 0);

    for (int t = 0; t < NT; t++) {
        if (t + 1 < NT) {
            load_tile(t + 1, (t + 1) & 1);
            asm volatile("cp.async.wait_group 1;");
        } else {
            asm volatile("cp.async.wait_group 0;");
        }
        __syncthreads();

        const float* As = sm + (t & 1)*STAGE_FLOATS;
        const float* Bs = As + A_STAGE;

        #pragma unroll
        for (int kk = 0; kk < BKT; kk += 8) {
            unsigned a[2][4];
            #pragma unroll
            for (int i = 0; i < 2; i++) {
                int r = wm*32 + i*16 + (lane >> 2);
                int c = kk + (lane & 3);
                a[i][0] = __float_as_uint(As[r*AS_STRIDE + c]);
                a[i][1] = __float_as_uint(As[(r+8)*AS_STRIDE + c]);
                a[i][2] = __float_as_uint(As[r*AS_STRIDE + c + 4]);
                a[i][3] = __float_as_uint(As[(r+8)*AS_STRIDE + c + 4]);
            }
            unsigned b[8][2];
            #pragma unroll
            for (int j = 0; j < 8; j++) {
                int n  = wn*64 + j*8 + (lane >> 2);
                int r0 = kk + (lane & 3);
                int r1 = r0 + 4;
                b[j][0] = __float_as_uint(Bs[r0*BN + (n ^ ((r0 & 3) << 3))]);
                b[j][1] = __float_as_uint(Bs[r1*BN + (n ^ ((r1 & 3) << 3))]);
            }
            #pragma unroll
            for (int i = 0; i < 2; i++)
                #pragma unroll
                for (int j = 0; j < 8; j++)
                    asm volatile(
                        "mma.sync.aligned.m16n8k8.row.col.f32.tf32.tf32.f32 "
                        "{%0,%1,%2,%3}, {%4,%5,%6,%7}, {%8,%9}, {%0,%1,%2,%3};"
                        : "+f"(acc[i][j][0]), "+f"(acc[i][j][1]),
                          "+f"(acc[i][j][2]), "+f"(acc[i][j][3])
                        : "r"(a[i][0]), "r"(a[i][1]), "r"(a[i][2]), "r"(a[i][3]),
                          "r"(b[j][0]), "r"(b[j][1]));
        }
        __syncthreads();
    }

    #pragma unroll
    for (int i = 0; i < 2; i++) {
        int r = row0 + wm*32 + i*16 + (lane >> 2);
        #pragma unroll
        for (int j = 0; j < 8; j++) {
            int c = col0 + wn*64 + j*8 + (lane & 3)*2;
            float b0 = bias[c], b1 = bias[c+1];
            float v0 = acc[i][j][0] + b0, v1 = acc[i][j][1] + b1;
            float v2 = acc[i][j][2] + b0, v3 = acc[i][j][3] + b1;
            if (round_out) {
                v0 = __uint_as_float(f2tf32(v0));
                v1 = __uint_as_float(f2tf32(v1));
                v2 = __uint_as_float(f2tf32(v2));
                v3 = __uint_as_float(f2tf32(v3));
            }
            C[(size_t)r*N + c]       = v0;
            C[(size_t)r*N + c + 1]   = v1;
            C[(size_t)(r+8)*N + c]   = v2;
            C[(size_t)(r+8)*N + c+1] = v3;
        }
    }
}

// ---------------------------------------------------------------------------
// Tensor-core flash attention (causal), tf32 MMA + online softmax.
// R4: q-tile 64, 4 warps/CTA, 104KB smem -> 2 CTAs/SM, grid 1024 CTAs,
// heavy-first scheduling, single __syncthreads per kv-iter.
// smem: Qs[64][68], Ks[2][64][68], Vs[2][64][72], Ps[64][68]
// ---------------------------------------------------------------------------
#define AQ_LD 68
#define AK_LD 68
#define AV_LD 72
#define AP_LD 68
#define Q_FLOATS (64*AQ_LD)
#define K_FLOATS (64*AK_LD)
#define V_FLOATS (64*AV_LD)
#define P_FLOATS (64*AP_LD)
#define ATTN_SMEM ((Q_FLOATS + 2*K_FLOATS + 2*V_FLOATS + P_FLOATS)*(int)sizeof(float))

__global__ void __launch_bounds__(128, 2)
flash_tc_kernel(const float* __restrict__ Q, const float* __restrict__ K,
                const float* __restrict__ V, float* __restrict__ O)
{
    extern __shared__ float sm[];
    float* Qs  = sm;
    float* Ks0 = Qs  + Q_FLOATS;
    float* Vs0 = Ks0 + 2*K_FLOATS;
    float* Ps  = Vs0 + 2*V_FLOATS;

    const int tid  = threadIdx.x;
    const int lane = tid & 31;
    const int warp = tid >> 5;            // 0..3
    const int qb   = (int)gridDim.x - 1 - (int)blockIdx.x;  // heavy-first: 31..0
    const int bh   = blockIdx.y;          // 0..31
    const int b    = bh >> 4;
    const int h    = bh & 15;
    const int q0   = qb * 64;
    const int qrow = warp * 16;           // warp's local q base
    const float SCL = 0.125f * 1.4426950408889634f;  // scale * log2(e)

    const size_t base = (size_t)b * TT * DIMC + (size_t)h * HD;

    // Q tile: 64 x 64 -> 1024 float4, 8 per thread (cp.async)
    #pragma unroll
    for (int i = 0; i < 8; i++) {
        int idx = tid + i*128;
        int r = idx >> 4, c4 = idx & 15;
        const float* src = Q + base + (size_t)(q0 + r)*DIMC + c4*4;
        unsigned dst = (unsigned)__cvta_generic_to_shared(&Qs[r*AQ_LD + c4*4]);
        asm volatile("cp.async.cg.shared.global [%0], [%1], 16;" :: "r"(dst), "l"(src));
    }

    auto load_kv = [&](int it, int s) {
        const int k0 = it * 64;
        float* Ks = Ks0 + s*K_FLOATS;
        float* Vs = Vs0 + s*V_FLOATS;
        #pragma unroll
        for (int i = 0; i < 8; i++) {
            int idx = tid + i*128;
            int r = idx >> 4, c4 = idx & 15;
            const float* srck = K + base + (size_t)(k0 + r)*DIMC + c4*4;
            unsigned dstk = (unsigned)__cvta_generic_to_shared(&Ks[r*AK_LD + c4*4]);
            asm volatile("cp.async.cg.shared.global [%0], [%1], 16;" :: "r"(dstk), "l"(srck));
            const float* srcv = V + base + (size_t)(k0 + r)*DIMC + c4*4;
            unsigned dstv = (unsigned)__cvta_generic_to_shared(&Vs[r*AV_LD + c4*4]);
            asm volatile("cp.async.cg.shared.global [%0], [%1], 16;" :: "r"(dstv), "l"(srcv));
        }
        asm volatile("cp.async.commit_group;");
    };

    const int niter = qb + 1;
    load_kv(0, 0);     // same commit group as Q

    // Per-thread state: rows r0 = lane>>2 and r0+8 of the warp tile
    float m[2] = {-1e30f, -1e30f};
    float l[2] = {0.f, 0.f};
    float o[8][4];
    #pragma unroll
    for (int j = 0; j < 8; j++)
        #pragma unroll
        for (int q = 0; q < 4; q++) o[j][q] = 0.f;

    for (int it = 0; it < niter; it++) {
        asm volatile("cp.async.wait_group 0;");
        __syncthreads();   // stage ready + all warps done with the buffer being reloaded
        if (it + 1 < niter) load_kv(it + 1, (it + 1) & 1);

        const float* Ks = Ks0 + (it & 1)*K_FLOATS;
        const float* Vs = Vs0 + (it & 1)*V_FLOATS;
        const int k0 = it * 64;

        // ---- S = Q @ K^T : 8 n-tiles (kv) x 8 k-steps (d) ----
        float s[8][4];
        #pragma unroll
        for (int j = 0; j < 8; j++)
            #pragma unroll
            for (int q = 0; q < 4; q++) s[j][q] = 0.f;

        #pragma unroll
        for (int kk = 0; kk < 8; kk++) {
            unsigned a[4];
            {
                int r = qrow + (lane >> 2);
                int c = kk*8 + (lane & 3);
                a[0] = __float_as_uint(Qs[r*AQ_LD + c]);
                a[1] = __float_as_uint(Qs[(r+8)*AQ_LD + c]);
                a[2] = __float_as_uint(Qs[r*AQ_LD + c + 4]);
                a[3] = __float_as_uint(Qs[(r+8)*AQ_LD + c + 4]);
            }
            #pragma unroll
            for (int j = 0; j < 8; j++) {
                int kv = j*8 + (lane >> 2);
                int d  = kk*8 + (lane & 3);
                unsigned b0 = __float_as_uint(Ks[kv*AK_LD + d]);
                unsigned b1 = __float_as_uint(Ks[kv*AK_LD + d + 4]);
                asm volatile(
                    "mma.sync.aligned.m16n8k8.row.col.f32.tf32.tf32.f32 "
                    "{%0,%1,%2,%3}, {%4,%5,%6,%7}, {%8,%9}, {%0,%1,%2,%3};"
                    : "+f"(s[j][0]), "+f"(s[j][1]), "+f"(s[j][2]), "+f"(s[j][3])
                    : "r"(a[0]), "r"(a[1]), "r"(a[2]), "r"(a[3]),
                      "r"(b0), "r"(b1));
            }
        }

        // ---- scale (exp2 domain) + causal mask ----
        const bool need_mask = (k0 + 63 > q0 + qrow);
        if (need_mask) {
            #pragma unroll
            for (int j = 0; j < 8; j++) {
                int kvb = k0 + j*8 + 2*(lane & 3);
                int qg0 = q0 + qrow + (lane >> 2);
                int qg1 = qg0 + 8;
                s[j][0] = (kvb     <= qg0) ? s[j][0]*SCL : -1e30f;
                s[j][1] = (kvb + 1 <= qg0) ? s[j][1]*SCL : -1e30f;
                s[j][2] = (kvb     <= qg1) ? s[j][2]*SCL : -1e30f;
                s[j][3] = (kvb + 1 <= qg1) ? s[j][3]*SCL : -1e30f;
            }
        } else {
            #pragma unroll
            for (int j = 0; j < 8; j++)
                #pragma unroll
                for (int q = 0; q < 4; q++) s[j][q] *= SCL;
        }

        // ---- online softmax (2 rows per thread) ----
        #pragma unroll
        for (int row = 0; row < 2; row++) {
            float mx = -1e30f;
            #pragma unroll
            for (int j = 0; j < 8; j++)
                mx = fmaxf(mx, fmaxf(s[j][row*2], s[j][row*2+1]));
            mx = fmaxf(mx, __shfl_xor_sync(0xffffffffu, mx, 1));
            mx = fmaxf(mx, __shfl_xor_sync(0xffffffffu, mx, 2));
            float mnew = fmaxf(m[row], mx);
            float corr = fexp2(m[row] - mnew);
            m[row] = mnew;
            float rs = 0.f;
            #pragma unroll
            for (int j = 0; j < 8; j++) {
                float p0 = fexp2(s[j][row*2]   - mnew);
                float p1 = fexp2(s[j][row*2+1] - mnew);
                s[j][row*2]   = p0;
                s[j][row*2+1] = p1;
                rs += p0 + p1;
            }
            rs += __shfl_xor_sync(0xffffffffu, rs, 1);
            rs += __shfl_xor_sync(0xffffffffu, rs, 2);
            l[row] = l[row]*corr + rs;
            #pragma unroll
            for (int j = 0; j < 8; j++) {
                o[j][row*2]   *= corr;
                o[j][row*2+1] *= corr;
            }
        }

        // ---- stage P (tf32-rounded) to smem for the PV MMA ----
        #pragma unroll
        for (int j = 0; j < 8; j++) {
            int r0 = qrow + (lane >> 2);
            int c  = j*8 + 2*(lane & 3);
            float2 p01 = make_float2(__uint_as_float(f2tf32(s[j][0])),
                                     __uint_as_float(f2tf32(s[j][1])));
            float2 p23 = make_float2(__uint_as_float(f2tf32(s[j][2])),
                                     __uint_as_float(f2tf32(s[j][3])));
            *reinterpret_cast<float2*>(&Ps[r0*AP_LD + c])     = p01;
            *reinterpret_cast<float2*>(&Ps[(r0+8)*AP_LD + c]) = p23;
        }
        __syncwarp();

        // ---- O += P @ V : 8 n-tiles (d) x 8 k-steps (kv) ----
        #pragma unroll
        for (int kk = 0; kk < 8; kk++) {
            unsigned a[4];
            {
                int r = qrow + (lane >> 2);
                int c = kk*8 + (lane & 3);
                a[0] = __float_as_uint(Ps[r*AP_LD + c]);
                a[1] = __float_as_uint(Ps[(r+8)*AP_LD + c]);
                a[2] = __float_as_uint(Ps[r*AP_LD + c + 4]);
                a[3] = __float_as_uint(Ps[(r+8)*AP_LD + c + 4]);
            }
            #pragma unroll
            for (int j = 0; j < 8; j++) {
                int kv = kk*8 + (lane & 3);
                int d  = j*8 + (lane >> 2);
                unsigned b0 = __float_as_uint(Vs[kv*AV_LD + d]);
                unsigned b1 = __float_as_uint(Vs[(kv+4)*AV_LD + d]);
                asm volatile(
                    "mma.sync.aligned.m16n8k8.row.col.f32.tf32.tf32.f32 "
                    "{%0,%1,%2,%3}, {%4,%5,%6,%7}, {%8,%9}, {%0,%1,%2,%3};"
                    : "+f"(o[j][0]), "+f"(o[j][1]), "+f"(o[j][2]), "+f"(o[j][3])
                    : "r"(a[0]), "r"(a[1]), "r"(a[2]), "r"(a[3]),
                      "r"(b0), "r"(b1));
            }
        }
        __syncwarp();   // P/Vs reads done before next iter's writes
    }

    // ---- normalize + write ctx (tf32-rounded; feeds Wo GEMM) ----
    #pragma unroll
    for (int row = 0; row < 2; row++) {
        float inv = 1.f / l[row];
        int r = q0 + qrow + (lane >> 2) + row*8;
        #pragma unroll
        for (int j = 0; j < 8; j++) {
            int c = j*8 + 2*(lane & 3);
            float2 v;
            v.x = __uint_as_float(f2tf32(o[j][row*2]   * inv));
            v.y = __uint_as_float(f2tf32(o[j][row*2+1] * inv));
            *reinterpret_cast<float2*>(&O[base + (size_t)r*DIMC + c]) = v;
        }
    }
}

// ---------------------------------------------------------------------------
extern "C" void kernel_launch(void* const* d_in, const int* in_sizes, int n_in,
                              void* d_out, int out_size)
{
    (void)in_sizes; (void)n_in; (void)out_size;
    const float* x  = (const float*)d_in[0];
    const float* Wq = (const float*)d_in[1];
    const float* bq = (const float*)d_in[2];
    const float* Wk = (const float*)d_in[3];
    const float* bk = (const float*)d_in[4];
    const float* Wv = (const float*)d_in[5];
    const float* bv = (const float*)d_in[6];
    const float* Wo = (const float*)d_in[7];
    const float* bo = (const float*)d_in[8];
    float* out = (float*)d_out;

    float *QKVp, *Cp, *Xc, *Wc;
    cudaGetSymbolAddress((void**)&QKVp, g_QKV);
    cudaGetSymbolAddress((void**)&Cp,   g_Ctx);
    cudaGetSymbolAddress((void**)&Xc,   g_Xc);
    cudaGetSymbolAddress((void**)&Wc,   g_Wc);

    cudaFuncSetAttribute(gemm_tf32_bias,
                         cudaFuncAttributeMaxDynamicSharedMemorySize, GEMM_SMEM);
    cudaFuncSetAttribute(flash_tc_kernel,
                         cudaFuncAttributeMaxDynamicSharedMemorySize, ATTN_SMEM);

    const int NTOT = MROWS*DIMC + 4*DIMC*DIMC;   // 8M
    cvt_all_kernel<<<NTOT/256, 256>>>(x, Wq, Wk, Wv, Wo, Xc, Wc);

    const int NW = DIMC*DIMC;
    const int MD = MROWS*DIMC;

    // fused QKV projections (grid.z selects weight), outputs tf32-rounded
    dim3 ggrid3(DIMC / BN, MROWS / BM, 3);
    gemm_tf32_bias<<<ggrid3, 256, GEMM_SMEM>>>(Xc, Wc, bq, bk, bv, QKVp,
                                               MROWS, DIMC, DIMC, 1);

    dim3 agrid(TT / 64, BB * NH);        // (32, 32) = 1024 CTAs
    flash_tc_kernel<<<agrid, 128, ATTN_SMEM>>>(QKVp, QKVp + MD, QKVp + 2*MD, Cp);

    dim3 ggrid1(DIMC / BN, MROWS / BM, 1);
    gemm_tf32_bias<<<ggrid1, 256, GEMM_SMEM>>>(Cp, Wc + 3*NW, bo, bo, bo, out,
                                               MROWS, DIMC, DIMC, 0);
}

// round 5
// speedup vs baseline: 7.4325x; 1.8688x over previous
#include <cuda_runtime.h>
#include <cuda_fp16.h>
#include <cstdint>

#define DIMC 1024
#define NH   16
#define HD   64
#define BB   2
#define TT   2048
#define MROWS (BB*TT)   // 4096

// Scratch (allocation-free rule: __device__ globals)
__device__ __half g_Xh[MROWS*DIMC];        // fp16 x
__device__ __half g_Wt[4*DIMC*DIMC];       // fp16 transposed weights [n][k]
__device__ __half g_QKVh[3*MROWS*DIMC];    // fp16 Q,K,V
__device__ __half g_Ctxh[MROWS*DIMC];      // fp16 attention output

__device__ __forceinline__ float fexp2(float x) {
    float y;
    asm("ex2.approx.f32 %0, %1;" : "=f"(y) : "f"(x));
    return y;
}
__device__ __forceinline__ void ldsm4(unsigned& r0, unsigned& r1,
                                      unsigned& r2, unsigned& r3, unsigned addr) {
    asm volatile("ldmatrix.sync.aligned.m8n8.x4.shared.b16 {%0,%1,%2,%3}, [%4];"
                 : "=r"(r0), "=r"(r1), "=r"(r2), "=r"(r3) : "r"(addr));
}
__device__ __forceinline__ void ldsm4t(unsigned& r0, unsigned& r1,
                                       unsigned& r2, unsigned& r3, unsigned addr) {
    asm volatile("ldmatrix.sync.aligned.m8n8.x4.trans.shared.b16 {%0,%1,%2,%3}, [%4];"
                 : "=r"(r0), "=r"(r1), "=r"(r2), "=r"(r3) : "r"(addr));
}
#define MMA16816(d0,d1,d2,d3,a0,a1,a2,a3,b0,b1)                              \
    asm volatile("mma.sync.aligned.m16n8k16.row.col.f32.f16.f16.f32 "        \
                 "{%0,%1,%2,%3}, {%4,%5,%6,%7}, {%8,%9}, {%0,%1,%2,%3};"     \
                 : "+f"(d0), "+f"(d1), "+f"(d2), "+f"(d3)                    \
                 : "r"(a0), "r"(a1), "r"(a2), "r"(a3), "r"(b0), "r"(b1))

__device__ __forceinline__ unsigned packh2(float lo, float hi) {
    __half2 h = __floats2half2_rn(lo, hi);
    return *reinterpret_cast<unsigned*>(&h);
}

// ---------------------------------------------------------------------------
// Pre-pass 1: x -> fp16
// ---------------------------------------------------------------------------
__global__ void cvt_x_kernel(const float* __restrict__ x, __half* __restrict__ xh)
{
    int i = (blockIdx.x*blockDim.x + threadIdx.x) * 2;
    float2 v = *reinterpret_cast<const float2*>(x + i);
    *reinterpret_cast<__half2*>(xh + i) = __floats2half2_rn(v.x, v.y);
}

// ---------------------------------------------------------------------------
// Pre-pass 2: transpose + fp16 the 4 weights: Wt[n][k] = (half)W[k][n]
// ---------------------------------------------------------------------------
__global__ void transpose_w_kernel(const float* __restrict__ wq,
                                   const float* __restrict__ wk,
                                   const float* __restrict__ wv,
                                   const float* __restrict__ wo,
                                   __half* __restrict__ wt)
{
    __shared__ __half tile[32][33];
    const int w = blockIdx.z;
    const float* src = (w == 0) ? wq : (w == 1) ? wk : (w == 2) ? wv : wo;
    __half* dst = wt + (size_t)w * DIMC * DIMC;
    const int n0 = blockIdx.x * 32;
    const int k0 = blockIdx.y * 32;
    const int tx = threadIdx.x, ty = threadIdx.y;   // 32 x 8
    #pragma unroll
    for (int i = 0; i < 4; i++)
        tile[ty + 8*i][tx] = __float2half_rn(src[(size_t)(k0 + ty + 8*i)*DIMC + n0 + tx]);
    __syncthreads();
    #pragma unroll
    for (int i = 0; i < 4; i++)
        dst[(size_t)(n0 + ty + 8*i)*DIMC + k0 + tx] = tile[tx][ty + 8*i];
}

// ---------------------------------------------------------------------------
// FP16 tensor-core GEMM (fp32 accum): C[M,N] = A[M,K] @ Wt[z][N,K]^T + bias[z]
// BM=128, BN=128, BK=32, 256 threads (8 warps 4x2), warp tile 32x64,
// mma.m16n8k16 + ldmatrix, cp.async double-buffered.
// A smem [m][k] stride 40 halves; B smem [n][k] stride 40 halves (both
// conflict-free for ldmatrix: 5r mod 8 is a permutation).
// ---------------------------------------------------------------------------
#define BM 128
#define BN 128
#define BKT 32
#define LDH 40
#define A_STAGEH (BM*LDH)                  // 5120 halves
#define B_STAGEH (BN*LDH)
#define STAGE_HALVES (A_STAGEH + B_STAGEH) // 10240
#define GEMM_SMEM (2*STAGE_HALVES*(int)sizeof(__half))   // 40960 B

__global__ void __launch_bounds__(256, 2)
gemm_h16(const __half* __restrict__ A, const __half* __restrict__ Wtall,
         const float* __restrict__ b0p, const float* __restrict__ b1p,
         const float* __restrict__ b2p,
         __half* __restrict__ Chbase, float* __restrict__ Cf,
         int M, int N, int K, int write_half)
{
    extern __shared__ __half smh[];
    const int z = blockIdx.z;
    const __half* Wt   = Wtall + (size_t)z*N*K;
    const float*  bias = (z == 0) ? b0p : (z == 1) ? b1p : b2p;

    const int tid  = threadIdx.x;
    const int lane = tid & 31;
    const int warp = tid >> 5;
    const int wm   = warp >> 1;           // 0..3
    const int wn   = warp & 1;            // 0..1
    const int row0 = blockIdx.y * BM;
    const int col0 = blockIdx.x * BN;

    float acc[2][8][4];
    #pragma unroll
    for (int i = 0; i < 2; i++)
        #pragma unroll
        for (int j = 0; j < 8; j++)
            #pragma unroll
            for (int q = 0; q < 4; q++) acc[i][j][q] = 0.f;

    const int NT = K / BKT;               // 32

    auto load_tile = [&](int kt, int s) {
        __half* As = smh + s*STAGE_HALVES;
        __half* Bs = As + A_STAGEH;
        #pragma unroll
        for (int i = 0; i < 2; i++) {
            int idx = tid + i*256;
            int r = idx >> 2, c = idx & 3;         // 128 rows x 4 16B-chunks
            const __half* src = A + (size_t)(row0 + r)*K + kt*BKT + c*8;
            unsigned dst = (unsigned)__cvta_generic_to_shared(&As[r*LDH + c*8]);
            asm volatile("cp.async.cg.shared.global [%0], [%1], 16;" :: "r"(dst), "l"(src));
        }
        #pragma unroll
        for (int i = 0; i < 2; i++) {
            int idx = tid + i*256;
            int r = idx >> 2, c = idx & 3;
            const __half* src = Wt + (size_t)(col0 + r)*K + kt*BKT + c*8;
            unsigned dst = (unsigned)__cvta_generic_to_shared(&Bs[r*LDH + c*8]);
            asm volatile("cp.async.cg.shared.global [%0], [%1], 16;" :: "r"(dst), "l"(src));
        }
        asm volatile("cp.async.commit_group;");
    };

    // per-lane ldmatrix offsets (halves)
    int a_off[2], b_off[4];
    #pragma unroll
    for (int i = 0; i < 2; i++)
        a_off[i] = (wm*32 + i*16 + (lane & 15))*LDH + (lane >> 4)*8;
    #pragma unroll
    for (int t = 0; t < 4; t++)
        b_off[t] = (wn*64 + t*16 + (lane & 7) + ((lane >> 4) << 3))*LDH
                 + ((lane >> 3) & 1)*8;

    load_tile(0, 0);

    for (int t = 0; t < NT; t++) {
        if (t + 1 < NT) {
            load_tile(t + 1, (t + 1) & 1);
            asm volatile("cp.async.wait_group 1;");
        } else {
            asm volatile("cp.async.wait_group 0;");
        }
        __syncthreads();

        const __half* As = smh + (t & 1)*STAGE_HALVES;
        const __half* Bs = As + A_STAGEH;
        unsigned as_u = (unsigned)__cvta_generic_to_shared(As);
        unsigned bs_u = (unsigned)__cvta_generic_to_shared(Bs);

        #pragma unroll
        for (int kk = 0; kk < 2; kk++) {
            unsigned a[2][4], b[4][4];
            #pragma unroll
            for (int i = 0; i < 2; i++)
                ldsm4(a[i][0], a[i][1], a[i][2], a[i][3],
                      as_u + (a_off[i] + kk*16)*2);
            #pragma unroll
            for (int g = 0; g < 4; g++)
                ldsm4(b[g][0], b[g][1], b[g][2], b[g][3],
                      bs_u + (b_off[g] + kk*16)*2);
            #pragma unroll
            for (int i = 0; i < 2; i++)
                #pragma unroll
                for (int j = 0; j < 8; j++)
                    MMA16816(acc[i][j][0], acc[i][j][1], acc[i][j][2], acc[i][j][3],
                             a[i][0], a[i][1], a[i][2], a[i][3],
                             b[j >> 1][(j & 1)*2], b[j >> 1][(j & 1)*2 + 1]);
        }
        __syncthreads();
    }

    __half* Ch = Chbase + (size_t)z*M*N;
    #pragma unroll
    for (int i = 0; i < 2; i++) {
        int r = row0 + wm*32 + i*16 + (lane >> 2);
        #pragma unroll
        for (int j = 0; j < 8; j++) {
            int c = col0 + wn*64 + j*8 + (lane & 3)*2;
            float b0 = bias[c], b1 = bias[c+1];
            float v0 = acc[i][j][0] + b0, v1 = acc[i][j][1] + b1;
            float v2 = acc[i][j][2] + b0, v3 = acc[i][j][3] + b1;
            if (write_half) {
                *reinterpret_cast<__half2*>(&Ch[(size_t)r*N + c])     = __floats2half2_rn(v0, v1);
                *reinterpret_cast<__half2*>(&Ch[(size_t)(r+8)*N + c]) = __floats2half2_rn(v2, v3);
            } else {
                Cf[(size_t)r*N + c]       = v0;
                Cf[(size_t)r*N + c + 1]   = v1;
                Cf[(size_t)(r+8)*N + c]   = v2;
                Cf[(size_t)(r+8)*N + c+1] = v3;
            }
        }
    }
}

// ---------------------------------------------------------------------------
// FP16 tensor-core flash attention (causal), fp32 softmax/accum.
// 4 warps/CTA, q-tile 64, kv blocks 64, D=64. P stays in registers (the
// m16n8k16 C-fragment layout IS the next A-fragment layout).
// smem: Qs[64][72], Ks[2][64][72], Vs[2][64][72] halves -> 46080 B, 3 CTAs/SM.
// ---------------------------------------------------------------------------
#define FLD 72
#define TILE_H (64*FLD)
#define ATTN_SMEM (5*TILE_H*(int)sizeof(__half))

__global__ void __launch_bounds__(128, 3)
flash_h16_kernel(const __half* __restrict__ Q, const __half* __restrict__ K,
                 const __half* __restrict__ V, __half* __restrict__ O)
{
    extern __shared__ __half smh[];
    __half* Qs  = smh;
    __half* Ks0 = Qs  + TILE_H;
    __half* Vs0 = Ks0 + 2*TILE_H;

    const int tid  = threadIdx.x;
    const int lane = tid & 31;
    const int warp = tid >> 5;            // 0..3
    const int qb   = (int)gridDim.x - 1 - (int)blockIdx.x;  // heavy-first
    const int bh   = blockIdx.y;
    const int b    = bh >> 4;
    const int h    = bh & 15;
    const int q0   = qb * 64;
    const int qrow = warp * 16;
    const float SCL = 0.125f * 1.4426950408889634f;

    const size_t base = (size_t)b * TT * DIMC + (size_t)h * HD;

    // Q tile: 64 x 64 halves = 512 16B-chunks, 4/thread
    #pragma unroll
    for (int i = 0; i < 4; i++) {
        int idx = tid + i*128;
        int r = idx >> 3, c = idx & 7;
        const __half* src = Q + base + (size_t)(q0 + r)*DIMC + c*8;
        unsigned dst = (unsigned)__cvta_generic_to_shared(&Qs[r*FLD + c*8]);
        asm volatile("cp.async.cg.shared.global [%0], [%1], 16;" :: "r"(dst), "l"(src));
    }

    auto load_kv = [&](int it, int s) {
        const int k0 = it * 64;
        __half* Ks = Ks0 + s*TILE_H;
        __half* Vs = Vs0 + s*TILE_H;
        #pragma unroll
        for (int i = 0; i < 4; i++) {
            int idx = tid + i*128;
            int r = idx >> 3, c = idx & 7;
            const __half* srck = K + base + (size_t)(k0 + r)*DIMC + c*8;
            unsigned dstk = (unsigned)__cvta_generic_to_shared(&Ks[r*FLD + c*8]);
            asm volatile("cp.async.cg.shared.global [%0], [%1], 16;" :: "r"(dstk), "l"(srck));
            const __half* srcv = V + base + (size_t)(k0 + r)*DIMC + c*8;
            unsigned dstv = (unsigned)__cvta_generic_to_shared(&Vs[r*FLD + c*8]);
            asm volatile("cp.async.cg.shared.global [%0], [%1], 16;" :: "r"(dstv), "l"(srcv));
        }
        asm volatile("cp.async.commit_group;");
    };

    const int niter = qb + 1;
    load_kv(0, 0);

    // per-lane ldmatrix offsets (halves)
    const int qa_off = (qrow + (lane & 15))*FLD + (lane >> 4)*8;   // Q A-frag, +kk*16
    int kb_off[4], vb_off[4];
    #pragma unroll
    for (int t = 0; t < 4; t++) {
        kb_off[t] = (t*16 + (lane & 7) + ((lane >> 4) << 3))*FLD + ((lane >> 3) & 1)*8;
        vb_off[t] = ((lane & 7) + (((lane >> 3) & 1) << 3))*FLD + t*16 + (lane >> 4)*8;
    }

    float m[2] = {-1e30f, -1e30f};
    float l[2] = {0.f, 0.f};
    float o[8][4];
    #pragma unroll
    for (int j = 0; j < 8; j++)
        #pragma unroll
        for (int q = 0; q < 4; q++) o[j][q] = 0.f;

    for (int it = 0; it < niter; it++) {
        asm volatile("cp.async.wait_group 0;");
        __syncthreads();
        if (it + 1 < niter) load_kv(it + 1, (it + 1) & 1);

        const __half* Ks = Ks0 + (it & 1)*TILE_H;
        const __half* Vs = Vs0 + (it & 1)*TILE_H;
        unsigned qs_u = (unsigned)__cvta_generic_to_shared(Qs);
        unsigned ks_u = (unsigned)__cvta_generic_to_shared(Ks);
        unsigned vs_u = (unsigned)__cvta_generic_to_shared(Vs);
        const int k0 = it * 64;

        // ---- S = Q @ K^T : k = d (4 x k16), n = kv (8 tiles) ----
        float s[8][4];
        #pragma unroll
        for (int j = 0; j < 8; j++)
            #pragma unroll
            for (int q = 0; q < 4; q++) s[j][q] = 0.f;

        #pragma unroll
        for (int kk = 0; kk < 4; kk++) {
            unsigned a[4], kb[4][4];
            ldsm4(a[0], a[1], a[2], a[3], qs_u + (qa_off + kk*16)*2);
            #pragma unroll
            for (int g = 0; g < 4; g++)
                ldsm4(kb[g][0], kb[g][1], kb[g][2], kb[g][3],
                      ks_u + (kb_off[g] + kk*16)*2);
            #pragma unroll
            for (int j = 0; j < 8; j++)
                MMA16816(s[j][0], s[j][1], s[j][2], s[j][3],
                         a[0], a[1], a[2], a[3],
                         kb[j >> 1][(j & 1)*2], kb[j >> 1][(j & 1)*2 + 1]);
        }

        // ---- scale (exp2 domain) + causal mask ----
        const bool need_mask = (k0 + 63 > q0 + qrow);
        if (need_mask) {
            #pragma unroll
            for (int j = 0; j < 8; j++) {
                int kvb = k0 + j*8 + 2*(lane & 3);
                int qg0 = q0 + qrow + (lane >> 2);
                int qg1 = qg0 + 8;
                s[j][0] = (kvb     <= qg0) ? s[j][0]*SCL : -1e30f;
                s[j][1] = (kvb + 1 <= qg0) ? s[j][1]*SCL : -1e30f;
                s[j][2] = (kvb     <= qg1) ? s[j][2]*SCL : -1e30f;
                s[j][3] = (kvb + 1 <= qg1) ? s[j][3]*SCL : -1e30f;
            }
        } else {
            #pragma unroll
            for (int j = 0; j < 8; j++)
                #pragma unroll
                for (int q = 0; q < 4; q++) s[j][q] *= SCL;
        }

        // ---- online softmax (2 rows/thread) ----
        #pragma unroll
        for (int row = 0; row < 2; row++) {
            float mx = -1e30f;
            #pragma unroll
            for (int j = 0; j < 8; j++)
                mx = fmaxf(mx, fmaxf(s[j][row*2], s[j][row*2+1]));
            mx = fmaxf(mx, __shfl_xor_sync(0xffffffffu, mx, 1));
            mx = fmaxf(mx, __shfl_xor_sync(0xffffffffu, mx, 2));
            float mnew = fmaxf(m[row], mx);
            float corr = fexp2(m[row] - mnew);
            m[row] = mnew;
            float rs = 0.f;
            #pragma unroll
            for (int j = 0; j < 8; j++) {
                float p0 = fexp2(s[j][row*2]   - mnew);
                float p1 = fexp2(s[j][row*2+1] - mnew);
                s[j][row*2]   = p0;
                s[j][row*2+1] = p1;
                rs += p0 + p1;
            }
            rs += __shfl_xor_sync(0xffffffffu, rs, 1);
            rs += __shfl_xor_sync(0xffffffffu, rs, 2);
            l[row] = l[row]*corr + rs;
            #pragma unroll
            for (int j = 0; j < 8; j++) {
                o[j][row*2]   *= corr;
                o[j][row*2+1] *= corr;
            }
        }

        // ---- O += P @ V : P from registers, V via ldmatrix.trans ----
        #pragma unroll
        for (int kk = 0; kk < 4; kk++) {
            unsigned pa[4];
            pa[0] = packh2(s[2*kk][0],   s[2*kk][1]);
            pa[1] = packh2(s[2*kk][2],   s[2*kk][3]);
            pa[2] = packh2(s[2*kk+1][0], s[2*kk+1][1]);
            pa[3] = packh2(s[2*kk+1][2], s[2*kk+1][3]);
            unsigned vb[4][4];
            #pragma unroll
            for (int g = 0; g < 4; g++)
                ldsm4t(vb[g][0], vb[g][1], vb[g][2], vb[g][3],
                       vs_u + (vb_off[g] + kk*16*FLD)*2);
            #pragma unroll
            for (int j = 0; j < 8; j++)
                MMA16816(o[j][0], o[j][1], o[j][2], o[j][3],
                         pa[0], pa[1], pa[2], pa[3],
                         vb[j >> 1][(j & 1)*2], vb[j >> 1][(j & 1)*2 + 1]);
        }
    }

    // ---- normalize + write ctx (fp16, [B,T,H*D] fuses head transpose) ----
    #pragma unroll
    for (int row = 0; row < 2; row++) {
        float inv = 1.f / l[row];
        int r = q0 + qrow + (lane >> 2) + row*8;
        #pragma unroll
        for (int j = 0; j < 8; j++) {
            int c = j*8 + 2*(lane & 3);
            *reinterpret_cast<__half2*>(&O[base + (size_t)r*DIMC + c]) =
                __floats2half2_rn(o[j][row*2] * inv, o[j][row*2+1] * inv);
        }
    }
}

// ---------------------------------------------------------------------------
extern "C" void kernel_launch(void* const* d_in, const int* in_sizes, int n_in,
                              void* d_out, int out_size)
{
    (void)in_sizes; (void)n_in; (void)out_size;
    const float* x  = (const float*)d_in[0];
    const float* Wq = (const float*)d_in[1];
    const float* bq = (const float*)d_in[2];
    const float* Wk = (const float*)d_in[3];
    const float* bk = (const float*)d_in[4];
    const float* Wv = (const float*)d_in[5];
    const float* bv = (const float*)d_in[6];
    const float* Wo = (const float*)d_in[7];
    const float* bo = (const float*)d_in[8];
    float* out = (float*)d_out;

    __half *Xh, *Wt, *QKVh, *Ctxh;
    cudaGetSymbolAddress((void**)&Xh,   g_Xh);
    cudaGetSymbolAddress((void**)&Wt,   g_Wt);
    cudaGetSymbolAddress((void**)&QKVh, g_QKVh);
    cudaGetSymbolAddress((void**)&Ctxh, g_Ctxh);

    cudaFuncSetAttribute(gemm_h16,
                         cudaFuncAttributeMaxDynamicSharedMemorySize, GEMM_SMEM);
    cudaFuncSetAttribute(flash_h16_kernel,
                         cudaFuncAttributeMaxDynamicSharedMemorySize, ATTN_SMEM);

    // prepass: fp16 conversions + weight transpose
    cvt_x_kernel<<<(MROWS*DIMC/2)/256, 256>>>(x, Xh);
    dim3 tgrid(DIMC/32, DIMC/32, 4);
    transpose_w_kernel<<<tgrid, dim3(32, 8)>>>(Wq, Wk, Wv, Wo, Wt);

    const size_t NW = (size_t)DIMC*DIMC;
    const size_t MD = (size_t)MROWS*DIMC;

    // fused QKV projections (grid.z selects weight), fp16 out
    dim3 ggrid3(DIMC/BN, MROWS/BM, 3);
    gemm_h16<<<ggrid3, 256, GEMM_SMEM>>>(Xh, Wt, bq, bk, bv, QKVh, out,
                                         MROWS, DIMC, DIMC, 1);

    dim3 agrid(TT/64, BB*NH);            // (32, 32)
    flash_h16_kernel<<<agrid, 128, ATTN_SMEM>>>(QKVh, QKVh + MD, QKVh + 2*MD, Ctxh);

    // output projection, fp32 out
    dim3 ggrid1(DIMC/BN, MROWS/BM, 1);
    gemm_h16<<<ggrid1, 256, GEMM_SMEM>>>(Ctxh, Wt + 3*NW, bo, bo, bo,
                                         QKVh /*unused*/, out,
                                         MROWS, DIMC, DIMC, 0);
}